// round 10
// baseline (speedup 1.0000x reference)
#include <cuda_runtime.h>
#include <cuda_bf16.h>
#include <cstdint>

#define NNODES 100000
#define NEDGES 800000
#define DH 96
#define C4 (DH / 4)

// ---- scratch ----
__device__ float g_H[NNODES * DH];      // layer-1 Hs: dis[r] * (x@W1)[r]
__device__ float g_H2[NNODES * DH];     // layer-2 Hs: dis[r] * (relu(agg1+b1)@W2)[r]
__device__ float g_dis[NNODES];
__device__ int   g_cntcur[2 * NNODES];  // [0,N): cnt, [N,2N): cur  (one memset)
__device__ int   g_off[NNODES];         // per-chunk exclusive prefix (bsum NOT applied)
__device__ int   g_bsum[256];           // exclusive chunk sums
__device__ int   g_csr[NEDGES];
// B fragments: [layer][var(hi/lo)][np(2)][kt(6)][nt(6)][lane(32)] -> uint2
__device__ uint2 g_Bfrag[2 * 2 * 2 * 6 * 6 * 32];

#define WPREP_TOTAL (2 * 2 * 2 * 6 * 6 * 32)     // 9216
#define WPREP_BLOCKS ((WPREP_TOTAL + 255) / 256) // 36
#define HIST_BLOCKS ((NEDGES + 255) / 256)       // 3125
#define GBM 128
#define GEMM_BLOCKS ((NNODES + GBM - 1) / GBM)   // 782

// ============================ helpers ============================

__device__ __forceinline__ uint32_t cvt_bf16x2(float lo, float hi) {
    uint32_t r;
    asm("cvt.rn.satfinite.bf16x2.f32 %0, %1, %2;" : "=r"(r) : "f"(hi), "f"(lo));
    return r;
}

__device__ __forceinline__ void mma_bf16(float* c, const uint32_t* a,
                                         uint32_t b0, uint32_t b1) {
    asm volatile(
        "mma.sync.aligned.m16n8k16.row.col.f32.bf16.bf16.f32 "
        "{%0,%1,%2,%3}, {%4,%5,%6,%7}, {%8,%9}, {%0,%1,%2,%3};"
        : "+f"(c[0]), "+f"(c[1]), "+f"(c[2]), "+f"(c[3])
        : "r"(a[0]), "r"(a[1]), "r"(a[2]), "r"(a[3]), "r"(b0), "r"(b1));
}

// ============================ W fragment prep ============================

__device__ __forceinline__ void wprep_body(int idx, const float* __restrict__ W1,
                                           const float* __restrict__ W2) {
    if (idx >= WPREP_TOTAL) return;
    int lane = idx & 31;
    int t = idx >> 5;
    int nt = t % 6;  t /= 6;
    int kt = t % 6;  t /= 6;
    int np = t % 2;  t /= 2;
    int var = t % 2; t /= 2;
    int layer = t;
    const float* W = layer ? W2 : W1;

    int n  = np * 48 + nt * 8 + (lane >> 2);
    int k0 = kt * 16 + (lane & 3) * 2;
    float v[4];
#pragma unroll
    for (int i = 0; i < 4; i++) {
        int k = k0 + (i & 1) + (i >> 1) * 8;
        float w = W[k * DH + n];
        float hi = __bfloat162float(__float2bfloat16(w));
        v[i] = var ? (w - hi) : hi;
    }
    g_Bfrag[idx] = make_uint2(cvt_bf16x2(v[0], v[1]), cvt_bf16x2(v[2], v[3]));
}

__global__ void hist_wprep_kernel(const int* __restrict__ ei,
                                  const float* __restrict__ W1,
                                  const float* __restrict__ W2) {
    if (blockIdx.x < WPREP_BLOCKS) {
        wprep_body(blockIdx.x * blockDim.x + threadIdx.x, W1, W2);
    } else {
        int e = (blockIdx.x - WPREP_BLOCKS) * blockDim.x + threadIdx.x;
        if (e < NEDGES) atomicAdd(&g_cntcur[ei[NEDGES + e]], 1);
    }
}

// ============================ scans + fill ============================

#define SCHUNK 512
#define NSBLK ((NNODES + SCHUNK - 1) / SCHUNK)   // 196

__global__ void scan1_kernel() {
    __shared__ int wsum[16];
    const int t = threadIdx.x;
    const int lane = t & 31, warp = t >> 5;
    const int i = blockIdx.x * SCHUNK + t;
    const int v = (i < NNODES) ? g_cntcur[i] : 0;
    int x = v;
#pragma unroll
    for (int o = 1; o < 32; o <<= 1) {
        int y = __shfl_up_sync(0xFFFFFFFF, x, o);
        if (lane >= o) x += y;
    }
    if (lane == 31) wsum[warp] = x;
    __syncthreads();
    if (warp == 0) {
        int s = (lane < 16) ? wsum[lane] : 0;
#pragma unroll
        for (int o = 1; o < 16; o <<= 1) {
            int y = __shfl_up_sync(0xFFFFFFFF, s, o);
            if (lane >= o) s += y;
        }
        if (lane < 16) wsum[lane] = s;
    }
    __syncthreads();
    const int base = (warp > 0) ? wsum[warp - 1] : 0;
    if (i < NNODES) {
        g_off[i] = base + x - v;
        g_dis[i] = rsqrtf((float)v + 1.0f);
    }
    if (t == SCHUNK - 1) g_bsum[blockIdx.x] = base + x;
}

__global__ void scan2_kernel() {   // single warp, 7 chunk totals per lane
    const int lane = threadIdx.x;
    const int base = lane * 7;
    int v[7], inc[7];
    int tot = 0;
#pragma unroll
    for (int j = 0; j < 7; j++) {
        v[j] = (base + j < NSBLK) ? g_bsum[base + j] : 0;
        tot += v[j];
        inc[j] = tot;
    }
    int x = tot;
#pragma unroll
    for (int o = 1; o < 32; o <<= 1) {
        int y = __shfl_up_sync(0xFFFFFFFF, x, o);
        if (lane >= o) x += y;
    }
    const int excl = x - tot;
#pragma unroll
    for (int j = 0; j < 7; j++)
        if (base + j < NSBLK) g_bsum[base + j] = excl + inc[j] - v[j];
}

__global__ void fill_kernel(const int* __restrict__ ei) {
    int e = blockIdx.x * blockDim.x + threadIdx.x;
    if (e >= NEDGES) return;
    int s = ei[e];
    int d = ei[NEDGES + e];
    int pos = g_off[d] + g_bsum[d >> 9] + atomicAdd(&g_cntcur[NNODES + d], 1);
    g_csr[pos] = s;
}

// ============================ GEMM pieces (HMMA) ============================
// Hs[n,96] = dis[n] * (A'[n,96] @ W[96,96])

#define APITCH 104
#define AROW_BYTES (APITCH * 2)
#define SM_AHI 0
#define SM_ALO (GBM * AROW_BYTES)
#define GEMM_SMEM (2 * GBM * AROW_BYTES)

// mainloop + epilogue; A tiles already staged in smem (bf16 hi/lo, row-major)
__device__ __forceinline__ void gemm_compute(char* smem, int row0,
                                             const uint2* __restrict__ Bfrag,
                                             float* __restrict__ H) {
    const int tid = threadIdx.x;
    const int lane = tid & 31;
    const int wid = tid >> 5;
    const int wm = wid & 3;
    const int wn = wid >> 2;

    float acc[2][6][4];
#pragma unroll
    for (int m = 0; m < 2; m++)
#pragma unroll
        for (int nt = 0; nt < 6; nt++)
#pragma unroll
            for (int i = 0; i < 4; i++) acc[m][nt][i] = 0.0f;

    const int fr = (lane >> 2);
    const int fk = (lane & 3) * 2;

#pragma unroll
    for (int kt = 0; kt < 6; kt++) {
        uint32_t ahi[2][4], alo[2][4];
#pragma unroll
        for (int m = 0; m < 2; m++) {
            const int r = wm * 32 + m * 16 + fr;
            const int kb = (kt * 16 + fk) * 2;
            const char* ph = smem + SM_AHI + r * AROW_BYTES + kb;
            const char* pl = smem + SM_ALO + r * AROW_BYTES + kb;
            ahi[m][0] = *(const uint32_t*)ph;
            ahi[m][1] = *(const uint32_t*)(ph + 8 * AROW_BYTES);
            ahi[m][2] = *(const uint32_t*)(ph + 16);
            ahi[m][3] = *(const uint32_t*)(ph + 8 * AROW_BYTES + 16);
            alo[m][0] = *(const uint32_t*)pl;
            alo[m][1] = *(const uint32_t*)(pl + 8 * AROW_BYTES);
            alo[m][2] = *(const uint32_t*)(pl + 16);
            alo[m][3] = *(const uint32_t*)(pl + 8 * AROW_BYTES + 16);
        }
#pragma unroll
        for (int nt = 0; nt < 6; nt++) {
            const uint2 bhi = Bfrag[(((0 * 2 + wn) * 6 + kt) * 6 + nt) * 32 + lane];
            const uint2 blo = Bfrag[(((1 * 2 + wn) * 6 + kt) * 6 + nt) * 32 + lane];
#pragma unroll
            for (int m = 0; m < 2; m++) {
                mma_bf16(acc[m][nt], ahi[m], bhi.x, bhi.y);
                mma_bf16(acc[m][nt], ahi[m], blo.x, blo.y);
                mma_bf16(acc[m][nt], alo[m], bhi.x, bhi.y);
            }
        }
    }

#pragma unroll
    for (int m = 0; m < 2; m++) {
        const int r = row0 + wm * 32 + m * 16 + fr;
        const float d0 = (r < NNODES) ? g_dis[r] : 0.0f;
        const float d1 = (r + 8 < NNODES) ? g_dis[r + 8] : 0.0f;
#pragma unroll
        for (int nt = 0; nt < 6; nt++) {
            const int col = wn * 48 + nt * 8 + fk;
            if (r < NNODES)
                *(float2*)(H + (size_t)r * DH + col) =
                    make_float2(acc[m][nt][0] * d0, acc[m][nt][1] * d0);
            if (r + 8 < NNODES)
                *(float2*)(H + (size_t)(r + 8) * DH + col) =
                    make_float2(acc[m][nt][2] * d1, acc[m][nt][3] * d1);
        }
    }
}

// layer-1 GEMM: stage A from gmem (fp32 x), split bf16, then compute -> g_H
__global__ void __launch_bounds__(256)
gemm_hmma_kernel(const float* __restrict__ A, const uint2* __restrict__ Bfrag,
                 float* __restrict__ H) {
    extern __shared__ char smem[];
    const int tid = threadIdx.x;
    const int row0 = blockIdx.x * GBM;
    {
        const int r = tid >> 1;
        const int cb = (tid & 1) * 48;
        const int grow = row0 + r;
        char* phi = smem + SM_AHI + r * AROW_BYTES;
        char* plo = smem + SM_ALO + r * AROW_BYTES;
#pragma unroll
        for (int q = 0; q < 12; q++) {
            const int k0 = cb + q * 4;
            float4 v = (grow < NNODES)
                ? *(const float4*)(A + (size_t)grow * DH + k0)
                : make_float4(0.f, 0.f, 0.f, 0.f);
            uint32_t h01 = cvt_bf16x2(v.x, v.y);
            uint32_t h23 = cvt_bf16x2(v.z, v.w);
            float lx = v.x - __uint_as_float(h01 << 16);
            float ly = v.y - __uint_as_float(h01 & 0xFFFF0000u);
            float lz = v.z - __uint_as_float(h23 << 16);
            float lw = v.w - __uint_as_float(h23 & 0xFFFF0000u);
            *(uint2*)(phi + k0 * 2) = make_uint2(h01, h23);
            *(uint2*)(plo + k0 * 2) = make_uint2(cvt_bf16x2(lx, ly), cvt_bf16x2(lz, lw));
        }
    }
    __syncthreads();
    gemm_compute(smem, row0, Bfrag, H);
}

// ============================ fused gather1 + gemm2 ============================
// Each block owns nodes [row0, row0+128). Phase 1: each warp gathers 16 nodes
// from Hin (= g_H, read-only here), applies relu(dis*(self+sum) + b1), splits
// bf16 hi/lo straight into the GEMM A-tiles in smem (AGG never hits gmem).
// Phase 2: mma mainloop + epilogue -> Hout (= g_H2, disjoint buffer: no race).

__global__ void __launch_bounds__(256)
gather_gemm_kernel(const float* __restrict__ Hin, const float* __restrict__ bias,
                   const uint2* __restrict__ Bfrag, float* __restrict__ Hout) {
    extern __shared__ char smem[];
    const int lane = threadIdx.x & 31;
    const int wid = threadIdx.x >> 5;
    const int row0 = blockIdx.x * GBM;
    const bool active = lane < C4;

    const float4 b = active ? __ldg((const float4*)bias + lane)
                            : make_float4(0.f, 0.f, 0.f, 0.f);

#pragma unroll 1
    for (int i = 0; i < 16; i++) {
        const int r = wid * 16 + i;          // row within tile
        const int node = row0 + r;
        float4 acc = make_float4(0.f, 0.f, 0.f, 0.f);
        if (node < NNODES) {
            if (active)
                acc = __ldg((const float4*)&Hin[(size_t)node * DH] + lane);  // self
            const int start = g_off[node] + g_bsum[node >> 9];
            const int deg = g_cntcur[node];
#pragma unroll 4
            for (int e = 0; e < deg; e++) {
                int s = __ldg(&g_csr[start + e]);
                if (active) {
                    float4 h = __ldg((const float4*)&Hin[(size_t)s * DH] + lane);
                    acc.x += h.x; acc.y += h.y; acc.z += h.z; acc.w += h.w;
                }
            }
        }
        if (active) {
            float dd = (node < NNODES) ? g_dis[node] : 0.0f;
            float vx = fmaxf(acc.x * dd + b.x, 0.0f);
            float vy = fmaxf(acc.y * dd + b.y, 0.0f);
            float vz = fmaxf(acc.z * dd + b.z, 0.0f);
            float vw = fmaxf(acc.w * dd + b.w, 0.0f);
            if (node >= NNODES) { vx = vy = vz = vw = 0.0f; }
            uint32_t h01 = cvt_bf16x2(vx, vy);
            uint32_t h23 = cvt_bf16x2(vz, vw);
            float lx = vx - __uint_as_float(h01 << 16);
            float ly = vy - __uint_as_float(h01 & 0xFFFF0000u);
            float lz = vz - __uint_as_float(h23 << 16);
            float lw = vw - __uint_as_float(h23 & 0xFFFF0000u);
            *(uint2*)(smem + SM_AHI + r * AROW_BYTES + lane * 8) = make_uint2(h01, h23);
            *(uint2*)(smem + SM_ALO + r * AROW_BYTES + lane * 8) =
                make_uint2(cvt_bf16x2(lx, ly), cvt_bf16x2(lz, lw));
        }
    }
    __syncthreads();
    gemm_compute(smem, row0, Bfrag, Hout);
}

// ============================ final gather (layer 2) ============================
// One warp per node. out[d] = relu(dis[d] * (Hs2[d] + sum Hs2[s]) + b2)

__global__ void __launch_bounds__(256)
gather_kernel(const float* __restrict__ Hin, const float* __restrict__ bias,
              float* __restrict__ out) {
    int gwid = (blockIdx.x * blockDim.x + threadIdx.x) >> 5;
    int lid = threadIdx.x & 31;
    if (gwid >= NNODES) return;

    const bool active = lid < C4;
    float4 acc = make_float4(0.f, 0.f, 0.f, 0.f);
    if (active)
        acc = __ldg((const float4*)&Hin[(size_t)gwid * DH] + lid);   // self term

    int start = g_off[gwid] + g_bsum[gwid >> 9];
    int deg   = g_cntcur[gwid];
#pragma unroll 4
    for (int i = 0; i < deg; i++) {
        int s = __ldg(&g_csr[start + i]);
        if (active) {
            float4 h = __ldg((const float4*)&Hin[(size_t)s * DH] + lid);
            acc.x += h.x; acc.y += h.y; acc.z += h.z; acc.w += h.w;
        }
    }

    if (active) {
        float dd = g_dis[gwid];
        float4 b = __ldg((const float4*)bias + lid);
        acc.x = fmaxf(acc.x * dd + b.x, 0.0f);
        acc.y = fmaxf(acc.y * dd + b.y, 0.0f);
        acc.z = fmaxf(acc.z * dd + b.z, 0.0f);
        acc.w = fmaxf(acc.w * dd + b.w, 0.0f);
        ((float4*)(out + (size_t)gwid * DH))[lid] = acc;
    }
}

// ============================ launch ============================

extern "C" void kernel_launch(void* const* d_in, const int* in_sizes, int n_in,
                              void* d_out, int out_size) {
    const float* x  = (const float*)d_in[0];
    const int*   ei = (const int*)d_in[1];
    const float* W1 = (const float*)d_in[2];
    const float* b1 = (const float*)d_in[3];
    const float* W2 = (const float*)d_in[4];
    const float* b2 = (const float*)d_in[5];
    float* out = (float*)d_out;

    void *pH_v, *pH2_v, *pBf_v, *pCC_v;
    cudaGetSymbolAddress(&pH_v, g_H);
    cudaGetSymbolAddress(&pH2_v, g_H2);
    cudaGetSymbolAddress(&pBf_v, g_Bfrag);
    cudaGetSymbolAddress(&pCC_v, g_cntcur);
    float* pH  = (float*)pH_v;
    float* pH2 = (float*)pH2_v;
    const uint2* pBf = (const uint2*)pBf_v;

    cudaFuncSetAttribute(gemm_hmma_kernel,
                         cudaFuncAttributeMaxDynamicSharedMemorySize, GEMM_SMEM);
    cudaFuncSetAttribute(gather_gemm_kernel,
                         cudaFuncAttributeMaxDynamicSharedMemorySize, GEMM_SMEM);

    const int T = 256;
    int nBlkGath = (NNODES * 32 + T - 1) / T;

    // 1. zero cnt+cur
    cudaMemsetAsync(pCC_v, 0, 2 * NNODES * sizeof(int));
    // 2. hist || wprep
    hist_wprep_kernel<<<WPREP_BLOCKS + HIST_BLOCKS, T>>>(ei, W1, W2);
    // 3-4. scans (+ dis)
    scan1_kernel<<<NSBLK, SCHUNK>>>();
    scan2_kernel<<<1, 32>>>();
    // 5. CSR fill (full occupancy, standalone)
    fill_kernel<<<HIST_BLOCKS, T>>>(ei);
    // 6. layer-1 GEMM: g_H = dis * (x @ W1)
    gemm_hmma_kernel<<<GEMM_BLOCKS, T, GEMM_SMEM>>>(x, pBf, pH);
    // 7. fused gather1 + gemm2: g_H2 = dis * (relu(agg(g_H)+b1) @ W2)
    gather_gemm_kernel<<<GEMM_BLOCKS, T, GEMM_SMEM>>>(pH, b1, pBf + 4608, pH2);
    // 8. final gather (bias+relu) -> out
    gather_kernel<<<nBlkGath, T>>>(pH2, b2, out);
}

// round 11
// speedup vs baseline: 1.1794x; 1.1794x over previous
#include <cuda_runtime.h>
#include <cuda_bf16.h>
#include <cstdint>

#define NNODES 100000
#define NEDGES 800000
#define DH 96
#define C4 (DH / 4)

// ---- scratch ----
__device__ float g_H[NNODES * DH];      // Hs: dis[r] * (A'@W)[r]  (per layer)
__device__ float g_AGG[NNODES * DH];    // layer-1 aggregation (raw, pre-bias)
__device__ float g_dis[NNODES];
__device__ int   g_cntcur[2 * NNODES];  // [0,N): cnt, [N,2N): cur  (one memset)
__device__ int   g_off[NNODES];         // per-chunk exclusive prefix
__device__ int   g_bsum[256];           // exclusive chunk sums
__device__ int   g_csr[NEDGES];
// B fragments: [layer][var(hi/lo)][np(2)][kt(6)][nt(6)][lane(32)] -> uint2
__device__ uint2 g_Bfrag[2 * 2 * 2 * 6 * 6 * 32];

#define WPREP_TOTAL (2 * 2 * 2 * 6 * 6 * 32)     // 9216
#define WPREP_BLOCKS ((WPREP_TOTAL + 255) / 256) // 36
#define HIST_BLOCKS ((NEDGES + 255) / 256)       // 3125
#define GBM 128
#define GEMM_BLOCKS ((NNODES + GBM - 1) / GBM)   // 782

// ============================ helpers ============================

__device__ __forceinline__ uint32_t cvt_bf16x2(float lo, float hi) {
    uint32_t r;
    asm("cvt.rn.satfinite.bf16x2.f32 %0, %1, %2;" : "=r"(r) : "f"(hi), "f"(lo));
    return r;
}

__device__ __forceinline__ void mma_bf16(float* c, const uint32_t* a,
                                         uint32_t b0, uint32_t b1) {
    asm volatile(
        "mma.sync.aligned.m16n8k16.row.col.f32.bf16.bf16.f32 "
        "{%0,%1,%2,%3}, {%4,%5,%6,%7}, {%8,%9}, {%0,%1,%2,%3};"
        : "+f"(c[0]), "+f"(c[1]), "+f"(c[2]), "+f"(c[3])
        : "r"(a[0]), "r"(a[1]), "r"(a[2]), "r"(a[3]), "r"(b0), "r"(b1));
}

// ============================ W fragment prep ============================

__device__ __forceinline__ void wprep_body(int idx, const float* __restrict__ W1,
                                           const float* __restrict__ W2) {
    if (idx >= WPREP_TOTAL) return;
    int lane = idx & 31;
    int t = idx >> 5;
    int nt = t % 6;  t /= 6;
    int kt = t % 6;  t /= 6;
    int np = t % 2;  t /= 2;
    int var = t % 2; t /= 2;
    int layer = t;
    const float* W = layer ? W2 : W1;

    int n  = np * 48 + nt * 8 + (lane >> 2);
    int k0 = kt * 16 + (lane & 3) * 2;
    float v[4];
#pragma unroll
    for (int i = 0; i < 4; i++) {
        int k = k0 + (i & 1) + (i >> 1) * 8;
        float w = W[k * DH + n];
        float hi = __bfloat162float(__float2bfloat16(w));
        v[i] = var ? (w - hi) : hi;
    }
    g_Bfrag[idx] = make_uint2(cvt_bf16x2(v[0], v[1]), cvt_bf16x2(v[2], v[3]));
}

__global__ void hist_wprep_kernel(const int* __restrict__ ei,
                                  const float* __restrict__ W1,
                                  const float* __restrict__ W2) {
    if (blockIdx.x < WPREP_BLOCKS) {
        wprep_body(blockIdx.x * blockDim.x + threadIdx.x, W1, W2);
    } else {
        int e = (blockIdx.x - WPREP_BLOCKS) * blockDim.x + threadIdx.x;
        if (e < NEDGES) atomicAdd(&g_cntcur[ei[NEDGES + e]], 1);
    }
}

// ============================ scans + fill ============================

#define SCHUNK 512
#define NSBLK ((NNODES + SCHUNK - 1) / SCHUNK)   // 196

__global__ void scan1_kernel() {
    __shared__ int wsum[16];
    const int t = threadIdx.x;
    const int lane = t & 31, warp = t >> 5;
    const int i = blockIdx.x * SCHUNK + t;
    const int v = (i < NNODES) ? g_cntcur[i] : 0;
    int x = v;
#pragma unroll
    for (int o = 1; o < 32; o <<= 1) {
        int y = __shfl_up_sync(0xFFFFFFFF, x, o);
        if (lane >= o) x += y;
    }
    if (lane == 31) wsum[warp] = x;
    __syncthreads();
    if (warp == 0) {
        int s = (lane < 16) ? wsum[lane] : 0;
#pragma unroll
        for (int o = 1; o < 16; o <<= 1) {
            int y = __shfl_up_sync(0xFFFFFFFF, s, o);
            if (lane >= o) s += y;
        }
        if (lane < 16) wsum[lane] = s;
    }
    __syncthreads();
    const int base = (warp > 0) ? wsum[warp - 1] : 0;
    if (i < NNODES) {
        g_off[i] = base + x - v;
        g_dis[i] = rsqrtf((float)v + 1.0f);
    }
    if (t == SCHUNK - 1) g_bsum[blockIdx.x] = base + x;
}

__global__ void scan2_kernel() {   // single warp, 7 chunk totals per lane
    const int lane = threadIdx.x;
    const int base = lane * 7;
    int v[7], inc[7];
    int tot = 0;
#pragma unroll
    for (int j = 0; j < 7; j++) {
        v[j] = (base + j < NSBLK) ? g_bsum[base + j] : 0;
        tot += v[j];
        inc[j] = tot;
    }
    int x = tot;
#pragma unroll
    for (int o = 1; o < 32; o <<= 1) {
        int y = __shfl_up_sync(0xFFFFFFFF, x, o);
        if (lane >= o) x += y;
    }
    const int excl = x - tot;
#pragma unroll
    for (int j = 0; j < 7; j++)
        if (base + j < NSBLK) g_bsum[base + j] = excl + inc[j] - v[j];
}

__global__ void fill_kernel(const int* __restrict__ ei) {
    int e = blockIdx.x * blockDim.x + threadIdx.x;
    if (e >= NEDGES) return;
    int s = ei[e];
    int d = ei[NEDGES + e];
    int pos = g_off[d] + g_bsum[d >> 9] + atomicAdd(&g_cntcur[NNODES + d], 1);
    g_csr[pos] = s;
}

// ============================ GEMM (HMMA) ============================
// Hs[n,96] = dis[n] * (A'[n,96] @ W[96,96]), A' = fuse ? relu(A+bias) : A

#define APITCH 104
#define AROW_BYTES (APITCH * 2)
#define SM_AHI 0
#define SM_ALO (GBM * AROW_BYTES)
#define GEMM_SMEM (2 * GBM * AROW_BYTES)

__device__ __forceinline__ void gemm_compute(char* smem, int row0,
                                             const uint2* __restrict__ Bfrag,
                                             float* __restrict__ H) {
    const int tid = threadIdx.x;
    const int lane = tid & 31;
    const int wid = tid >> 5;
    const int wm = wid & 3;
    const int wn = wid >> 2;

    float acc[2][6][4];
#pragma unroll
    for (int m = 0; m < 2; m++)
#pragma unroll
        for (int nt = 0; nt < 6; nt++)
#pragma unroll
            for (int i = 0; i < 4; i++) acc[m][nt][i] = 0.0f;

    const int fr = (lane >> 2);
    const int fk = (lane & 3) * 2;

#pragma unroll
    for (int kt = 0; kt < 6; kt++) {
        uint32_t ahi[2][4], alo[2][4];
#pragma unroll
        for (int m = 0; m < 2; m++) {
            const int r = wm * 32 + m * 16 + fr;
            const int kb = (kt * 16 + fk) * 2;
            const char* ph = smem + SM_AHI + r * AROW_BYTES + kb;
            const char* pl = smem + SM_ALO + r * AROW_BYTES + kb;
            ahi[m][0] = *(const uint32_t*)ph;
            ahi[m][1] = *(const uint32_t*)(ph + 8 * AROW_BYTES);
            ahi[m][2] = *(const uint32_t*)(ph + 16);
            ahi[m][3] = *(const uint32_t*)(ph + 8 * AROW_BYTES + 16);
            alo[m][0] = *(const uint32_t*)pl;
            alo[m][1] = *(const uint32_t*)(pl + 8 * AROW_BYTES);
            alo[m][2] = *(const uint32_t*)(pl + 16);
            alo[m][3] = *(const uint32_t*)(pl + 8 * AROW_BYTES + 16);
        }
#pragma unroll
        for (int nt = 0; nt < 6; nt++) {
            const uint2 bhi = Bfrag[(((0 * 2 + wn) * 6 + kt) * 6 + nt) * 32 + lane];
            const uint2 blo = Bfrag[(((1 * 2 + wn) * 6 + kt) * 6 + nt) * 32 + lane];
#pragma unroll
            for (int m = 0; m < 2; m++) {
                mma_bf16(acc[m][nt], ahi[m], bhi.x, bhi.y);
                mma_bf16(acc[m][nt], ahi[m], blo.x, blo.y);
                mma_bf16(acc[m][nt], alo[m], bhi.x, bhi.y);
            }
        }
    }

#pragma unroll
    for (int m = 0; m < 2; m++) {
        const int r = row0 + wm * 32 + m * 16 + fr;
        const float d0 = (r < NNODES) ? g_dis[r] : 0.0f;
        const float d1 = (r + 8 < NNODES) ? g_dis[r + 8] : 0.0f;
#pragma unroll
        for (int nt = 0; nt < 6; nt++) {
            const int col = wn * 48 + nt * 8 + fk;
            if (r < NNODES)
                *(float2*)(H + (size_t)r * DH + col) =
                    make_float2(acc[m][nt][0] * d0, acc[m][nt][1] * d0);
            if (r + 8 < NNODES)
                *(float2*)(H + (size_t)(r + 8) * DH + col) =
                    make_float2(acc[m][nt][2] * d1, acc[m][nt][3] * d1);
        }
    }
}

// stage A from gmem fp32 (optionally relu(A+bias)), split bf16, compute
__global__ void __launch_bounds__(256)
gemm_hmma_kernel(const float* __restrict__ A, const uint2* __restrict__ Bfrag,
                 const float* __restrict__ bias, float* __restrict__ H, int fuse) {
    extern __shared__ char smem[];
    const int tid = threadIdx.x;
    const int row0 = blockIdx.x * GBM;
    {
        const int r = tid >> 1;
        const int cb = (tid & 1) * 48;
        const int grow = row0 + r;
        char* phi = smem + SM_AHI + r * AROW_BYTES;
        char* plo = smem + SM_ALO + r * AROW_BYTES;
#pragma unroll
        for (int q = 0; q < 12; q++) {
            const int k0 = cb + q * 4;
            float4 v;
            if (grow < NNODES) {
                v = *(const float4*)(A + (size_t)grow * DH + k0);
                if (fuse) {
                    const float4 b = *(const float4*)(bias + k0);
                    v.x = fmaxf(v.x + b.x, 0.0f);
                    v.y = fmaxf(v.y + b.y, 0.0f);
                    v.z = fmaxf(v.z + b.z, 0.0f);
                    v.w = fmaxf(v.w + b.w, 0.0f);
                }
            } else {
                v = make_float4(0.f, 0.f, 0.f, 0.f);
            }
            uint32_t h01 = cvt_bf16x2(v.x, v.y);
            uint32_t h23 = cvt_bf16x2(v.z, v.w);
            float lx = v.x - __uint_as_float(h01 << 16);
            float ly = v.y - __uint_as_float(h01 & 0xFFFF0000u);
            float lz = v.z - __uint_as_float(h23 << 16);
            float lw = v.w - __uint_as_float(h23 & 0xFFFF0000u);
            *(uint2*)(phi + k0 * 2) = make_uint2(h01, h23);
            *(uint2*)(plo + k0 * 2) = make_uint2(cvt_bf16x2(lx, ly), cvt_bf16x2(lz, lw));
        }
    }
    __syncthreads();
    gemm_compute(smem, row0, Bfrag, H);
}

// ============================ gather aggregation ============================
// One warp per node. r = dis[d] * (Hs[d] + sum_{s in N(d)} Hs[s])
// mode 0: out[d] = r (raw, bias applied later in gemm2's A-stage)
// mode 1: out[d] = relu(r + bias)

__global__ void __launch_bounds__(256)
gather_kernel(const float* __restrict__ Hin, const float* __restrict__ bias,
              float* __restrict__ out, int mode) {
    int gwid = (blockIdx.x * blockDim.x + threadIdx.x) >> 5;
    int lid = threadIdx.x & 31;
    if (gwid >= NNODES) return;

    const bool active = lid < C4;
    float4 acc = make_float4(0.f, 0.f, 0.f, 0.f);
    if (active)
        acc = __ldg((const float4*)&Hin[(size_t)gwid * DH] + lid);   // self term

    int start = g_off[gwid] + g_bsum[gwid >> 9];
    int deg   = g_cntcur[gwid];
#pragma unroll 4
    for (int i = 0; i < deg; i++) {
        int s = __ldg(&g_csr[start + i]);
        if (active) {
            float4 h = __ldg((const float4*)&Hin[(size_t)s * DH] + lid);
            acc.x += h.x; acc.y += h.y; acc.z += h.z; acc.w += h.w;
        }
    }

    if (active) {
        float dd = g_dis[gwid];
        acc.x *= dd; acc.y *= dd; acc.z *= dd; acc.w *= dd;
        if (mode == 1) {
            float4 b = __ldg((const float4*)bias + lid);
            acc.x = fmaxf(acc.x + b.x, 0.0f);
            acc.y = fmaxf(acc.y + b.y, 0.0f);
            acc.z = fmaxf(acc.z + b.z, 0.0f);
            acc.w = fmaxf(acc.w + b.w, 0.0f);
        }
        ((float4*)(out + (size_t)gwid * DH))[lid] = acc;
    }
}

// ============================ launch ============================

extern "C" void kernel_launch(void* const* d_in, const int* in_sizes, int n_in,
                              void* d_out, int out_size) {
    const float* x  = (const float*)d_in[0];
    const int*   ei = (const int*)d_in[1];
    const float* W1 = (const float*)d_in[2];
    const float* b1 = (const float*)d_in[3];
    const float* W2 = (const float*)d_in[4];
    const float* b2 = (const float*)d_in[5];
    float* out = (float*)d_out;

    void *pH_v, *pAGG_v, *pBf_v, *pCC_v;
    cudaGetSymbolAddress(&pH_v, g_H);
    cudaGetSymbolAddress(&pAGG_v, g_AGG);
    cudaGetSymbolAddress(&pBf_v, g_Bfrag);
    cudaGetSymbolAddress(&pCC_v, g_cntcur);
    float* pH   = (float*)pH_v;
    float* pAGG = (float*)pAGG_v;
    const uint2* pBf = (const uint2*)pBf_v;

    cudaFuncSetAttribute(gemm_hmma_kernel,
                         cudaFuncAttributeMaxDynamicSharedMemorySize, GEMM_SMEM);

    const int T = 256;
    int nBlkGath = (NNODES * 32 + T - 1) / T;

    // 1. zero cnt+cur
    cudaMemsetAsync(pCC_v, 0, 2 * NNODES * sizeof(int));
    // 2. hist || wprep (block-range split; both latency/atomic class, no smem)
    hist_wprep_kernel<<<WPREP_BLOCKS + HIST_BLOCKS, T>>>(ei, W1, W2);
    // 3-4. scans (+ dis)
    scan1_kernel<<<NSBLK, SCHUNK>>>();
    scan2_kernel<<<1, 32>>>();
    // 5. CSR fill (standalone, full occupancy)
    fill_kernel<<<HIST_BLOCKS, T>>>(ei);
    // 6. layer-1 GEMM: g_H = dis * (x @ W1)
    gemm_hmma_kernel<<<GEMM_BLOCKS, T, GEMM_SMEM>>>(x, pBf, nullptr, pH, 0);
    // 7. gather layer 1 -> AGG (raw)
    gather_kernel<<<nBlkGath, T>>>(pH, nullptr, pAGG, 0);
    // 8. layer-2 GEMM: g_H = dis * (relu(AGG+b1) @ W2)   (AGG fully read before write via kernel boundary)
    gemm_hmma_kernel<<<GEMM_BLOCKS, T, GEMM_SMEM>>>(pAGG, pBf + 4608, b1, pH, 1);
    // 9. gather layer 2 (bias+relu) -> out
    gather_kernel<<<nBlkGath, T>>>(pH, b2, out, 1);
}

// round 12
// speedup vs baseline: 1.2157x; 1.0308x over previous
#include <cuda_runtime.h>
#include <cuda_bf16.h>
#include <cstdint>

#define NNODES 100000
#define NEDGES 800000
#define DH 96
#define C4 (DH / 4)

// ---- scratch ----
__device__ float g_H[NNODES * DH];      // Hs: dis[r] * (A'@W)[r]  (per layer)
__device__ float g_AGG[NNODES * DH];    // layer-1 aggregation (raw, pre-bias)
__device__ float g_dis[NNODES];
__device__ int   g_cntcur[2 * NNODES];  // [0,N): cnt, [N,2N): cur  (one memset)
__device__ int   g_off[NNODES];         // per-chunk exclusive prefix
__device__ int   g_bsum[256];           // exclusive chunk sums
__device__ int   g_csr[NEDGES];
// B fragments: [layer][var(hi/lo)][np(2)][kt(6)][nt(6)][lane(32)] -> uint2
__device__ uint2 g_Bfrag[2 * 2 * 2 * 6 * 6 * 32];

#define WPREP_TOTAL (2 * 2 * 2 * 6 * 6 * 32)     // 9216
#define WPREP_BLOCKS ((WPREP_TOTAL + 255) / 256) // 36
#define HIST_BLOCKS ((NEDGES + 255) / 256)       // 3125
#define GBM 64
#define GEMM_BLOCKS ((NNODES + GBM - 1) / GBM)   // 1563
#define FILL_BLOCKS ((NEDGES / 4 + 255) / 256)   // 782

// ============================ helpers ============================

__device__ __forceinline__ uint32_t cvt_bf16x2(float lo, float hi) {
    uint32_t r;
    asm("cvt.rn.satfinite.bf16x2.f32 %0, %1, %2;" : "=r"(r) : "f"(hi), "f"(lo));
    return r;
}

__device__ __forceinline__ void mma_bf16(float* c, const uint32_t* a,
                                         uint32_t b0, uint32_t b1) {
    asm volatile(
        "mma.sync.aligned.m16n8k16.row.col.f32.bf16.bf16.f32 "
        "{%0,%1,%2,%3}, {%4,%5,%6,%7}, {%8,%9}, {%0,%1,%2,%3};"
        : "+f"(c[0]), "+f"(c[1]), "+f"(c[2]), "+f"(c[3])
        : "r"(a[0]), "r"(a[1]), "r"(a[2]), "r"(a[3]), "r"(b0), "r"(b1));
}

// ============================ W fragment prep ============================

__device__ __forceinline__ void wprep_body(int idx, const float* __restrict__ W1,
                                           const float* __restrict__ W2) {
    if (idx >= WPREP_TOTAL) return;
    int lane = idx & 31;
    int t = idx >> 5;
    int nt = t % 6;  t /= 6;
    int kt = t % 6;  t /= 6;
    int np = t % 2;  t /= 2;
    int var = t % 2; t /= 2;
    int layer = t;
    const float* W = layer ? W2 : W1;

    int n  = np * 48 + nt * 8 + (lane >> 2);
    int k0 = kt * 16 + (lane & 3) * 2;
    float v[4];
#pragma unroll
    for (int i = 0; i < 4; i++) {
        int k = k0 + (i & 1) + (i >> 1) * 8;
        float w = W[k * DH + n];
        float hi = __bfloat162float(__float2bfloat16(w));
        v[i] = var ? (w - hi) : hi;
    }
    g_Bfrag[idx] = make_uint2(cvt_bf16x2(v[0], v[1]), cvt_bf16x2(v[2], v[3]));
}

__global__ void hist_wprep_kernel(const int* __restrict__ ei,
                                  const float* __restrict__ W1,
                                  const float* __restrict__ W2) {
    if (blockIdx.x < WPREP_BLOCKS) {
        wprep_body(blockIdx.x * blockDim.x + threadIdx.x, W1, W2);
    } else {
        int e = (blockIdx.x - WPREP_BLOCKS) * blockDim.x + threadIdx.x;
        if (e < NEDGES) atomicAdd(&g_cntcur[ei[NEDGES + e]], 1);
    }
}

// ============================ scans + fill ============================

#define SCHUNK 512
#define NSBLK ((NNODES + SCHUNK - 1) / SCHUNK)   // 196

__global__ void scan1_kernel() {
    __shared__ int wsum[16];
    const int t = threadIdx.x;
    const int lane = t & 31, warp = t >> 5;
    const int i = blockIdx.x * SCHUNK + t;
    const int v = (i < NNODES) ? g_cntcur[i] : 0;
    int x = v;
#pragma unroll
    for (int o = 1; o < 32; o <<= 1) {
        int y = __shfl_up_sync(0xFFFFFFFF, x, o);
        if (lane >= o) x += y;
    }
    if (lane == 31) wsum[warp] = x;
    __syncthreads();
    if (warp == 0) {
        int s = (lane < 16) ? wsum[lane] : 0;
#pragma unroll
        for (int o = 1; o < 16; o <<= 1) {
            int y = __shfl_up_sync(0xFFFFFFFF, s, o);
            if (lane >= o) s += y;
        }
        if (lane < 16) wsum[lane] = s;
    }
    __syncthreads();
    const int base = (warp > 0) ? wsum[warp - 1] : 0;
    if (i < NNODES) {
        g_off[i] = base + x - v;
        g_dis[i] = rsqrtf((float)v + 1.0f);
    }
    if (t == SCHUNK - 1) g_bsum[blockIdx.x] = base + x;
}

__global__ void scan2_kernel() {   // single warp, 7 chunk totals per lane
    const int lane = threadIdx.x;
    const int base = lane * 7;
    int v[7], inc[7];
    int tot = 0;
#pragma unroll
    for (int j = 0; j < 7; j++) {
        v[j] = (base + j < NSBLK) ? g_bsum[base + j] : 0;
        tot += v[j];
        inc[j] = tot;
    }
    int x = tot;
#pragma unroll
    for (int o = 1; o < 32; o <<= 1) {
        int y = __shfl_up_sync(0xFFFFFFFF, x, o);
        if (lane >= o) x += y;
    }
    const int excl = x - tot;
#pragma unroll
    for (int j = 0; j < 7; j++)
        if (base + j < NSBLK) g_bsum[base + j] = excl + inc[j] - v[j];
}

// 4 edges per thread via int4: 4 independent LDG->ATOMG->STG chains (MLP),
// whole fill is one wave (200k threads).
__global__ void fill_kernel(const int* __restrict__ ei) {
    int t = blockIdx.x * blockDim.x + threadIdx.x;
    int e0 = t * 4;
    if (e0 >= NEDGES) return;     // NEDGES % 4 == 0: no partial int4
    int4 s4 = *(const int4*)(ei + e0);
    int4 d4 = *(const int4*)(ei + NEDGES + e0);
    int p0 = g_off[d4.x] + g_bsum[d4.x >> 9] + atomicAdd(&g_cntcur[NNODES + d4.x], 1);
    int p1 = g_off[d4.y] + g_bsum[d4.y >> 9] + atomicAdd(&g_cntcur[NNODES + d4.y], 1);
    int p2 = g_off[d4.z] + g_bsum[d4.z >> 9] + atomicAdd(&g_cntcur[NNODES + d4.z], 1);
    int p3 = g_off[d4.w] + g_bsum[d4.w >> 9] + atomicAdd(&g_cntcur[NNODES + d4.w], 1);
    g_csr[p0] = s4.x;
    g_csr[p1] = s4.y;
    g_csr[p2] = s4.z;
    g_csr[p3] = s4.w;
}

// ============================ GEMM (HMMA) ============================
// Hs[n,96] = dis[n] * (A'[n,96] @ W[96,96]), A' = fuse ? relu(A+bias) : A
// GBM=64: 8 warps = 2 M-part x 4 N-part, 26.6KB smem, ~4 CTA/SM.

#define APITCH 104
#define AROW_BYTES (APITCH * 2)
#define SM_AHI 0
#define SM_ALO (GBM * AROW_BYTES)
#define GEMM_SMEM (2 * GBM * AROW_BYTES)   // 26624

__device__ __forceinline__ void gemm_compute(char* smem, int row0,
                                             const uint2* __restrict__ Bfrag,
                                             float* __restrict__ H) {
    const int tid = threadIdx.x;
    const int lane = tid & 31;
    const int wid = tid >> 5;
    const int wm = wid & 1;            // M partition (32 rows)
    const int wn = wid >> 1;           // N partition (24 cols, 3 nt tiles)

    float acc[2][3][4];
#pragma unroll
    for (int m = 0; m < 2; m++)
#pragma unroll
        for (int nt = 0; nt < 3; nt++)
#pragma unroll
            for (int i = 0; i < 4; i++) acc[m][nt][i] = 0.0f;

    const int fr = (lane >> 2);
    const int fk = (lane & 3) * 2;

#pragma unroll
    for (int kt = 0; kt < 6; kt++) {
        uint32_t ahi[2][4], alo[2][4];
#pragma unroll
        for (int m = 0; m < 2; m++) {
            const int r = wm * 32 + m * 16 + fr;
            const int kb = (kt * 16 + fk) * 2;
            const char* ph = smem + SM_AHI + r * AROW_BYTES + kb;
            const char* pl = smem + SM_ALO + r * AROW_BYTES + kb;
            ahi[m][0] = *(const uint32_t*)ph;
            ahi[m][1] = *(const uint32_t*)(ph + 8 * AROW_BYTES);
            ahi[m][2] = *(const uint32_t*)(ph + 16);
            ahi[m][3] = *(const uint32_t*)(ph + 8 * AROW_BYTES + 16);
            alo[m][0] = *(const uint32_t*)pl;
            alo[m][1] = *(const uint32_t*)(pl + 8 * AROW_BYTES);
            alo[m][2] = *(const uint32_t*)(pl + 16);
            alo[m][3] = *(const uint32_t*)(pl + 8 * AROW_BYTES + 16);
        }
#pragma unroll
        for (int nt = 0; nt < 3; nt++) {
            const int g = wn * 3 + nt;          // global 8-col tile 0..11
            const int np = g / 6, n6 = g % 6;
            const uint2 bhi = Bfrag[(((0 * 2 + np) * 6 + kt) * 6 + n6) * 32 + lane];
            const uint2 blo = Bfrag[(((1 * 2 + np) * 6 + kt) * 6 + n6) * 32 + lane];
#pragma unroll
            for (int m = 0; m < 2; m++) {
                mma_bf16(acc[m][nt], ahi[m], bhi.x, bhi.y);
                mma_bf16(acc[m][nt], ahi[m], blo.x, blo.y);
                mma_bf16(acc[m][nt], alo[m], bhi.x, bhi.y);
            }
        }
    }

#pragma unroll
    for (int m = 0; m < 2; m++) {
        const int r = row0 + wm * 32 + m * 16 + fr;
        const float d0 = (r < NNODES) ? g_dis[r] : 0.0f;
        const float d1 = (r + 8 < NNODES) ? g_dis[r + 8] : 0.0f;
#pragma unroll
        for (int nt = 0; nt < 3; nt++) {
            const int col = (wn * 3 + nt) * 8 + fk;
            if (r < NNODES)
                *(float2*)(H + (size_t)r * DH + col) =
                    make_float2(acc[m][nt][0] * d0, acc[m][nt][1] * d0);
            if (r + 8 < NNODES)
                *(float2*)(H + (size_t)(r + 8) * DH + col) =
                    make_float2(acc[m][nt][2] * d1, acc[m][nt][3] * d1);
        }
    }
}

// stage A from gmem fp32 (optionally relu(A+bias)), split bf16, compute
__global__ void __launch_bounds__(256)
gemm_hmma_kernel(const float* __restrict__ A, const uint2* __restrict__ Bfrag,
                 const float* __restrict__ bias, float* __restrict__ H, int fuse) {
    extern __shared__ char smem[];
    const int tid = threadIdx.x;
    const int row0 = blockIdx.x * GBM;
    {
        const int r = tid >> 2;            // 0..63
        const int cb = (tid & 3) * 24;     // 24-col segment
        const int grow = row0 + r;
        char* phi = smem + SM_AHI + r * AROW_BYTES;
        char* plo = smem + SM_ALO + r * AROW_BYTES;
#pragma unroll
        for (int q = 0; q < 6; q++) {
            const int k0 = cb + q * 4;
            float4 v;
            if (grow < NNODES) {
                v = *(const float4*)(A + (size_t)grow * DH + k0);
                if (fuse) {
                    const float4 b = *(const float4*)(bias + k0);
                    v.x = fmaxf(v.x + b.x, 0.0f);
                    v.y = fmaxf(v.y + b.y, 0.0f);
                    v.z = fmaxf(v.z + b.z, 0.0f);
                    v.w = fmaxf(v.w + b.w, 0.0f);
                }
            } else {
                v = make_float4(0.f, 0.f, 0.f, 0.f);
            }
            uint32_t h01 = cvt_bf16x2(v.x, v.y);
            uint32_t h23 = cvt_bf16x2(v.z, v.w);
            float lx = v.x - __uint_as_float(h01 << 16);
            float ly = v.y - __uint_as_float(h01 & 0xFFFF0000u);
            float lz = v.z - __uint_as_float(h23 << 16);
            float lw = v.w - __uint_as_float(h23 & 0xFFFF0000u);
            *(uint2*)(phi + k0 * 2) = make_uint2(h01, h23);
            *(uint2*)(plo + k0 * 2) = make_uint2(cvt_bf16x2(lx, ly), cvt_bf16x2(lz, lw));
        }
    }
    __syncthreads();
    gemm_compute(smem, row0, Bfrag, H);
}

// ============================ gather aggregation ============================
// One warp per node. r = dis[d] * (Hs[d] + sum_{s in N(d)} Hs[s])
// mode 0: out[d] = r (raw; bias applied in gemm2's A-stage)
// mode 1: out[d] = relu(r + bias)

__global__ void __launch_bounds__(256)
gather_kernel(const float* __restrict__ Hin, const float* __restrict__ bias,
              float* __restrict__ out, int mode) {
    int gwid = (blockIdx.x * blockDim.x + threadIdx.x) >> 5;
    int lid = threadIdx.x & 31;
    if (gwid >= NNODES) return;

    const bool active = lid < C4;
    float4 acc = make_float4(0.f, 0.f, 0.f, 0.f);
    if (active)
        acc = __ldg((const float4*)&Hin[(size_t)gwid * DH] + lid);   // self term

    int start = g_off[gwid] + g_bsum[gwid >> 9];
    int deg   = g_cntcur[gwid];
#pragma unroll 4
    for (int i = 0; i < deg; i++) {
        int s = __ldg(&g_csr[start + i]);
        if (active) {
            float4 h = __ldg((const float4*)&Hin[(size_t)s * DH] + lid);
            acc.x += h.x; acc.y += h.y; acc.z += h.z; acc.w += h.w;
        }
    }

    if (active) {
        float dd = g_dis[gwid];
        acc.x *= dd; acc.y *= dd; acc.z *= dd; acc.w *= dd;
        if (mode == 1) {
            float4 b = __ldg((const float4*)bias + lid);
            acc.x = fmaxf(acc.x + b.x, 0.0f);
            acc.y = fmaxf(acc.y + b.y, 0.0f);
            acc.z = fmaxf(acc.z + b.z, 0.0f);
            acc.w = fmaxf(acc.w + b.w, 0.0f);
        }
        ((float4*)(out + (size_t)gwid * DH))[lid] = acc;
    }
}

// ============================ launch ============================

extern "C" void kernel_launch(void* const* d_in, const int* in_sizes, int n_in,
                              void* d_out, int out_size) {
    const float* x  = (const float*)d_in[0];
    const int*   ei = (const int*)d_in[1];
    const float* W1 = (const float*)d_in[2];
    const float* b1 = (const float*)d_in[3];
    const float* W2 = (const float*)d_in[4];
    const float* b2 = (const float*)d_in[5];
    float* out = (float*)d_out;

    void *pH_v, *pAGG_v, *pBf_v, *pCC_v;
    cudaGetSymbolAddress(&pH_v, g_H);
    cudaGetSymbolAddress(&pAGG_v, g_AGG);
    cudaGetSymbolAddress(&pBf_v, g_Bfrag);
    cudaGetSymbolAddress(&pCC_v, g_cntcur);
    float* pH   = (float*)pH_v;
    float* pAGG = (float*)pAGG_v;
    const uint2* pBf = (const uint2*)pBf_v;

    cudaFuncSetAttribute(gemm_hmma_kernel,
                         cudaFuncAttributeMaxDynamicSharedMemorySize, GEMM_SMEM);

    const int T = 256;
    int nBlkGath = (NNODES * 32 + T - 1) / T;

    // 1. zero cnt+cur
    cudaMemsetAsync(pCC_v, 0, 2 * NNODES * sizeof(int));
    // 2. hist || wprep
    hist_wprep_kernel<<<WPREP_BLOCKS + HIST_BLOCKS, T>>>(ei, W1, W2);
    // 3-4. scans (+ dis)
    scan1_kernel<<<NSBLK, SCHUNK>>>();
    scan2_kernel<<<1, 32>>>();
    // 5. CSR fill (4 edges/thread, single wave)
    fill_kernel<<<FILL_BLOCKS, T>>>(ei);
    // 6. layer-1 GEMM: g_H = dis * (x @ W1)
    gemm_hmma_kernel<<<GEMM_BLOCKS, T, GEMM_SMEM>>>(x, pBf, nullptr, pH, 0);
    // 7. gather layer 1 -> AGG (raw)
    gather_kernel<<<nBlkGath, T>>>(pH, nullptr, pAGG, 0);
    // 8. layer-2 GEMM: g_H = dis * (relu(AGG+b1) @ W2)
    gemm_hmma_kernel<<<GEMM_BLOCKS, T, GEMM_SMEM>>>(pAGG, pBf + 4608, b1, pH, 1);
    // 9. gather layer 2 (bias+relu) -> out
    gather_kernel<<<nBlkGath, T>>>(pH, b2, out, 1);
}

// round 13
// speedup vs baseline: 1.3469x; 1.1079x over previous
#include <cuda_runtime.h>
#include <cuda_bf16.h>
#include <cuda_fp16.h>
#include <cstdint>

#define NNODES 100000
#define NEDGES 800000
#define DH 96
#define C4 (DH / 4)

// ---- scratch ----
__device__ __half g_H[NNODES * DH];     // Hs table (fp16): dis[r] * (A'@W)[r]
__device__ float  g_AGG[NNODES * DH];   // layer-1 aggregation (fp32, raw)
__device__ float  g_dis[NNODES];
__device__ int    g_cnt[NNODES];        // in-degree; hist doubles as slot cursor
__device__ int    g_epos[NEDGES];       // per-edge slot within its dst bucket
__device__ int    g_off[NNODES];        // per-chunk exclusive prefix
__device__ int    g_bsum[256];          // exclusive chunk sums
__device__ int    g_csr[NEDGES];
// B fragments: [layer][var(hi/lo)][np(2)][kt(6)][nt(6)][lane(32)] -> uint2
__device__ uint2  g_Bfrag[2 * 2 * 2 * 6 * 6 * 32];

#define WPREP_TOTAL (2 * 2 * 2 * 6 * 6 * 32)     // 9216
#define WPREP_BLOCKS ((WPREP_TOTAL + 255) / 256) // 36
#define HIST_BLOCKS ((NEDGES + 255) / 256)       // 3125
#define GBM 64
#define GEMM_BLOCKS ((NNODES + GBM - 1) / GBM)   // 1563

// ============================ helpers ============================

__device__ __forceinline__ uint32_t cvt_bf16x2(float lo, float hi) {
    uint32_t r;
    asm("cvt.rn.satfinite.bf16x2.f32 %0, %1, %2;" : "=r"(r) : "f"(hi), "f"(lo));
    return r;
}

__device__ __forceinline__ void mma_bf16(float* c, const uint32_t* a,
                                         uint32_t b0, uint32_t b1) {
    asm volatile(
        "mma.sync.aligned.m16n8k16.row.col.f32.bf16.bf16.f32 "
        "{%0,%1,%2,%3}, {%4,%5,%6,%7}, {%8,%9}, {%0,%1,%2,%3};"
        : "+f"(c[0]), "+f"(c[1]), "+f"(c[2]), "+f"(c[3])
        : "r"(a[0]), "r"(a[1]), "r"(a[2]), "r"(a[3]), "r"(b0), "r"(b1));
}

// ============================ W fragment prep ============================

__device__ __forceinline__ void wprep_body(int idx, const float* __restrict__ W1,
                                           const float* __restrict__ W2) {
    if (idx >= WPREP_TOTAL) return;
    int lane = idx & 31;
    int t = idx >> 5;
    int nt = t % 6;  t /= 6;
    int kt = t % 6;  t /= 6;
    int np = t % 2;  t /= 2;
    int var = t % 2; t /= 2;
    int layer = t;
    const float* W = layer ? W2 : W1;

    int n  = np * 48 + nt * 8 + (lane >> 2);
    int k0 = kt * 16 + (lane & 3) * 2;
    float v[4];
#pragma unroll
    for (int i = 0; i < 4; i++) {
        int k = k0 + (i & 1) + (i >> 1) * 8;
        float w = W[k * DH + n];
        float hi = __bfloat162float(__float2bfloat16(w));
        v[i] = var ? (w - hi) : hi;
    }
    g_Bfrag[idx] = make_uint2(cvt_bf16x2(v[0], v[1]), cvt_bf16x2(v[2], v[3]));
}

// hist (records per-edge slot) || wprep, block-range split
__global__ void hist_wprep_kernel(const int* __restrict__ ei,
                                  const float* __restrict__ W1,
                                  const float* __restrict__ W2) {
    if (blockIdx.x < WPREP_BLOCKS) {
        wprep_body(blockIdx.x * blockDim.x + threadIdx.x, W1, W2);
    } else {
        int e = (blockIdx.x - WPREP_BLOCKS) * blockDim.x + threadIdx.x;
        if (e < NEDGES) {
            int d = ei[NEDGES + e];
            g_epos[e] = atomicAdd(&g_cnt[d], 1);   // count AND slot in one atomic
        }
    }
}

// ============================ scans + fill ============================

#define SCHUNK 512
#define NSBLK ((NNODES + SCHUNK - 1) / SCHUNK)   // 196

__global__ void scan1_kernel() {
    __shared__ int wsum[16];
    const int t = threadIdx.x;
    const int lane = t & 31, warp = t >> 5;
    const int i = blockIdx.x * SCHUNK + t;
    const int v = (i < NNODES) ? g_cnt[i] : 0;
    int x = v;
#pragma unroll
    for (int o = 1; o < 32; o <<= 1) {
        int y = __shfl_up_sync(0xFFFFFFFF, x, o);
        if (lane >= o) x += y;
    }
    if (lane == 31) wsum[warp] = x;
    __syncthreads();
    if (warp == 0) {
        int s = (lane < 16) ? wsum[lane] : 0;
#pragma unroll
        for (int o = 1; o < 16; o <<= 1) {
            int y = __shfl_up_sync(0xFFFFFFFF, s, o);
            if (lane >= o) s += y;
        }
        if (lane < 16) wsum[lane] = s;
    }
    __syncthreads();
    const int base = (warp > 0) ? wsum[warp - 1] : 0;
    if (i < NNODES) {
        g_off[i] = base + x - v;
        g_dis[i] = rsqrtf((float)v + 1.0f);
    }
    if (t == SCHUNK - 1) g_bsum[blockIdx.x] = base + x;
}

__global__ void scan2_kernel() {   // single warp, 7 chunk totals per lane
    const int lane = threadIdx.x;
    const int base = lane * 7;
    int v[7], inc[7];
    int tot = 0;
#pragma unroll
    for (int j = 0; j < 7; j++) {
        v[j] = (base + j < NSBLK) ? g_bsum[base + j] : 0;
        tot += v[j];
        inc[j] = tot;
    }
    int x = tot;
#pragma unroll
    for (int o = 1; o < 32; o <<= 1) {
        int y = __shfl_up_sync(0xFFFFFFFF, x, o);
        if (lane >= o) x += y;
    }
    const int excl = x - tot;
#pragma unroll
    for (int j = 0; j < 7; j++)
        if (base + j < NSBLK) g_bsum[base + j] = excl + inc[j] - v[j];
}

// atomic-free fill: slot was captured during hist
__global__ void fill_kernel(const int* __restrict__ ei) {
    int e = blockIdx.x * blockDim.x + threadIdx.x;
    if (e >= NEDGES) return;
    int s = ei[e];
    int d = ei[NEDGES + e];
    int pos = g_off[d] + g_bsum[d >> 9] + g_epos[e];
    g_csr[pos] = s;
}

// ============================ GEMM (HMMA) ============================
// Hs[n,96] = dis[n] * (A'[n,96] @ W[96,96]) stored fp16; A' = fuse ? relu(A+bias) : A
// GBM=64: 8 warps = 2 M-part x 4 N-part, 26.6KB smem.

#define APITCH 104
#define AROW_BYTES (APITCH * 2)
#define SM_AHI 0
#define SM_ALO (GBM * AROW_BYTES)
#define GEMM_SMEM (2 * GBM * AROW_BYTES)   // 26624

__device__ __forceinline__ void gemm_compute(char* smem, int row0,
                                             const uint2* __restrict__ Bfrag,
                                             __half* __restrict__ H) {
    const int tid = threadIdx.x;
    const int lane = tid & 31;
    const int wid = tid >> 5;
    const int wm = wid & 1;            // M partition (32 rows)
    const int wn = wid >> 1;           // N partition (3 nt tiles of 8 cols)

    float acc[2][3][4];
#pragma unroll
    for (int m = 0; m < 2; m++)
#pragma unroll
        for (int nt = 0; nt < 3; nt++)
#pragma unroll
            for (int i = 0; i < 4; i++) acc[m][nt][i] = 0.0f;

    const int fr = (lane >> 2);
    const int fk = (lane & 3) * 2;

#pragma unroll
    for (int kt = 0; kt < 6; kt++) {
        uint32_t ahi[2][4], alo[2][4];
#pragma unroll
        for (int m = 0; m < 2; m++) {
            const int r = wm * 32 + m * 16 + fr;
            const int kb = (kt * 16 + fk) * 2;
            const char* ph = smem + SM_AHI + r * AROW_BYTES + kb;
            const char* pl = smem + SM_ALO + r * AROW_BYTES + kb;
            ahi[m][0] = *(const uint32_t*)ph;
            ahi[m][1] = *(const uint32_t*)(ph + 8 * AROW_BYTES);
            ahi[m][2] = *(const uint32_t*)(ph + 16);
            ahi[m][3] = *(const uint32_t*)(ph + 8 * AROW_BYTES + 16);
            alo[m][0] = *(const uint32_t*)pl;
            alo[m][1] = *(const uint32_t*)(pl + 8 * AROW_BYTES);
            alo[m][2] = *(const uint32_t*)(pl + 16);
            alo[m][3] = *(const uint32_t*)(pl + 8 * AROW_BYTES + 16);
        }
#pragma unroll
        for (int nt = 0; nt < 3; nt++) {
            const int g = wn * 3 + nt;          // global 8-col tile 0..11
            const int np = g / 6, n6 = g % 6;
            const uint2 bhi = Bfrag[(((0 * 2 + np) * 6 + kt) * 6 + n6) * 32 + lane];
            const uint2 blo = Bfrag[(((1 * 2 + np) * 6 + kt) * 6 + n6) * 32 + lane];
#pragma unroll
            for (int m = 0; m < 2; m++) {
                mma_bf16(acc[m][nt], ahi[m], bhi.x, bhi.y);
                mma_bf16(acc[m][nt], ahi[m], blo.x, blo.y);
                mma_bf16(acc[m][nt], alo[m], bhi.x, bhi.y);
            }
        }
    }

#pragma unroll
    for (int m = 0; m < 2; m++) {
        const int r = row0 + wm * 32 + m * 16 + fr;
        const float d0 = (r < NNODES) ? g_dis[r] : 0.0f;
        const float d1 = (r + 8 < NNODES) ? g_dis[r + 8] : 0.0f;
#pragma unroll
        for (int nt = 0; nt < 3; nt++) {
            const int col = (wn * 3 + nt) * 8 + fk;
            if (r < NNODES)
                *(__half2*)(H + (size_t)r * DH + col) =
                    __floats2half2_rn(acc[m][nt][0] * d0, acc[m][nt][1] * d0);
            if (r + 8 < NNODES)
                *(__half2*)(H + (size_t)(r + 8) * DH + col) =
                    __floats2half2_rn(acc[m][nt][2] * d1, acc[m][nt][3] * d1);
        }
    }
}

// stage A from gmem fp32 (optionally relu(A+bias)), split bf16, compute
__global__ void __launch_bounds__(256)
gemm_hmma_kernel(const float* __restrict__ A, const uint2* __restrict__ Bfrag,
                 const float* __restrict__ bias, __half* __restrict__ H, int fuse) {
    extern __shared__ char smem[];
    const int tid = threadIdx.x;
    const int row0 = blockIdx.x * GBM;
    {
        const int r = tid >> 2;            // 0..63
        const int cb = (tid & 3) * 24;     // 24-col segment
        const int grow = row0 + r;
        char* phi = smem + SM_AHI + r * AROW_BYTES;
        char* plo = smem + SM_ALO + r * AROW_BYTES;
#pragma unroll
        for (int q = 0; q < 6; q++) {
            const int k0 = cb + q * 4;
            float4 v;
            if (grow < NNODES) {
                v = *(const float4*)(A + (size_t)grow * DH + k0);
                if (fuse) {
                    const float4 b = *(const float4*)(bias + k0);
                    v.x = fmaxf(v.x + b.x, 0.0f);
                    v.y = fmaxf(v.y + b.y, 0.0f);
                    v.z = fmaxf(v.z + b.z, 0.0f);
                    v.w = fmaxf(v.w + b.w, 0.0f);
                }
            } else {
                v = make_float4(0.f, 0.f, 0.f, 0.f);
            }
            uint32_t h01 = cvt_bf16x2(v.x, v.y);
            uint32_t h23 = cvt_bf16x2(v.z, v.w);
            float lx = v.x - __uint_as_float(h01 << 16);
            float ly = v.y - __uint_as_float(h01 & 0xFFFF0000u);
            float lz = v.z - __uint_as_float(h23 << 16);
            float lw = v.w - __uint_as_float(h23 & 0xFFFF0000u);
            *(uint2*)(phi + k0 * 2) = make_uint2(h01, h23);
            *(uint2*)(plo + k0 * 2) = make_uint2(cvt_bf16x2(lx, ly), cvt_bf16x2(lz, lw));
        }
    }
    __syncthreads();
    gemm_compute(smem, row0, Bfrag, H);
}

// ============================ gather aggregation ============================
// One warp per node, fp16 H table, fp32 accumulation.
// r = dis[d] * (Hs[d] + sum_{s in N(d)} Hs[s])
// mode 0: out[d] = r (raw fp32; bias applied in gemm2's A-stage)
// mode 1: out[d] = relu(r + bias) (fp32 final output)

__global__ void __launch_bounds__(256)
gather_kernel(const __half* __restrict__ Hin, const float* __restrict__ bias,
              float* __restrict__ out, int mode) {
    int gwid = (blockIdx.x * blockDim.x + threadIdx.x) >> 5;
    int lid = threadIdx.x & 31;
    if (gwid >= NNODES) return;

    const bool active = lid < C4;
    float4 acc = make_float4(0.f, 0.f, 0.f, 0.f);
    if (active) {
        uint2 u = __ldg((const uint2*)(Hin + (size_t)gwid * DH) + lid);  // self
        float2 f0 = __half22float2(*reinterpret_cast<__half2*>(&u.x));
        float2 f1 = __half22float2(*reinterpret_cast<__half2*>(&u.y));
        acc = make_float4(f0.x, f0.y, f1.x, f1.y);
    }

    int start = g_off[gwid] + g_bsum[gwid >> 9];
    int deg   = g_cnt[gwid];
#pragma unroll 4
    for (int i = 0; i < deg; i++) {
        int s = __ldg(&g_csr[start + i]);
        if (active) {
            uint2 u = __ldg((const uint2*)(Hin + (size_t)s * DH) + lid);
            float2 f0 = __half22float2(*reinterpret_cast<__half2*>(&u.x));
            float2 f1 = __half22float2(*reinterpret_cast<__half2*>(&u.y));
            acc.x += f0.x; acc.y += f0.y; acc.z += f1.x; acc.w += f1.y;
        }
    }

    if (active) {
        float dd = g_dis[gwid];
        acc.x *= dd; acc.y *= dd; acc.z *= dd; acc.w *= dd;
        if (mode == 1) {
            float4 b = __ldg((const float4*)bias + lid);
            acc.x = fmaxf(acc.x + b.x, 0.0f);
            acc.y = fmaxf(acc.y + b.y, 0.0f);
            acc.z = fmaxf(acc.z + b.z, 0.0f);
            acc.w = fmaxf(acc.w + b.w, 0.0f);
        }
        ((float4*)(out + (size_t)gwid * DH))[lid] = acc;
    }
}

// ============================ launch ============================

extern "C" void kernel_launch(void* const* d_in, const int* in_sizes, int n_in,
                              void* d_out, int out_size) {
    const float* x  = (const float*)d_in[0];
    const int*   ei = (const int*)d_in[1];
    const float* W1 = (const float*)d_in[2];
    const float* b1 = (const float*)d_in[3];
    const float* W2 = (const float*)d_in[4];
    const float* b2 = (const float*)d_in[5];
    float* out = (float*)d_out;

    void *pH_v, *pAGG_v, *pBf_v, *pCnt_v;
    cudaGetSymbolAddress(&pH_v, g_H);
    cudaGetSymbolAddress(&pAGG_v, g_AGG);
    cudaGetSymbolAddress(&pBf_v, g_Bfrag);
    cudaGetSymbolAddress(&pCnt_v, g_cnt);
    __half* pH  = (__half*)pH_v;
    float* pAGG = (float*)pAGG_v;
    const uint2* pBf = (const uint2*)pBf_v;

    cudaFuncSetAttribute(gemm_hmma_kernel,
                         cudaFuncAttributeMaxDynamicSharedMemorySize, GEMM_SMEM);

    const int T = 256;
    int nBlkGath = (NNODES * 32 + T - 1) / T;

    // 1. zero cnt
    cudaMemsetAsync(pCnt_v, 0, NNODES * sizeof(int));
    // 2. hist (+ per-edge slot capture) || wprep
    hist_wprep_kernel<<<WPREP_BLOCKS + HIST_BLOCKS, T>>>(ei, W1, W2);
    // 3-4. scans (+ dis)
    scan1_kernel<<<NSBLK, SCHUNK>>>();
    scan2_kernel<<<1, 32>>>();
    // 5. CSR fill (atomic-free: pure load/scatter-store)
    fill_kernel<<<HIST_BLOCKS, T>>>(ei);
    // 6. layer-1 GEMM: g_H = fp16(dis * (x @ W1))
    gemm_hmma_kernel<<<GEMM_BLOCKS, T, GEMM_SMEM>>>(x, pBf, nullptr, pH, 0);
    // 7. gather layer 1 -> AGG (fp32 raw)
    gather_kernel<<<nBlkGath, T>>>(pH, nullptr, pAGG, 0);
    // 8. layer-2 GEMM: g_H = fp16(dis * (relu(AGG+b1) @ W2))
    gemm_hmma_kernel<<<GEMM_BLOCKS, T, GEMM_SMEM>>>(pAGG, pBf + 4608, b1, pH, 1);
    // 9. gather layer 2 (bias+relu) -> out (fp32)
    gather_kernel<<<nBlkGath, T>>>(pH, b2, out, 1);
}

// round 14
// speedup vs baseline: 1.4079x; 1.0453x over previous
#include <cuda_runtime.h>
#include <cuda_bf16.h>
#include <cuda_fp16.h>
#include <cstdint>

#define NNODES 100000
#define NEDGES 800000
#define DH 96
#define C4 (DH / 4)

// ---- scratch ----
__device__ __half g_H[NNODES * DH];     // Hs table (fp16): dis[r] * (A'@W)[r]
__device__ __half g_AGG[NNODES * DH];   // layer-1 activation (fp16): relu(agg+b1)
__device__ float  g_dis[NNODES];
__device__ int    g_cnt[NNODES];        // in-degree; hist doubles as slot cursor
__device__ int    g_epos[NEDGES];       // per-edge slot within its dst bucket
__device__ int    g_off[NNODES];        // per-chunk exclusive prefix
__device__ int    g_bsum[256];          // exclusive chunk sums
__device__ int    g_csr[NEDGES];
// B fragments: [layer][var(hi/lo)][np(2)][kt(6)][nt(6)][lane(32)] -> uint2
__device__ uint2  g_Bfrag[2 * 2 * 2 * 6 * 6 * 32];

#define WPREP_TOTAL (2 * 2 * 2 * 6 * 6 * 32)     // 9216
#define WPREP_BLOCKS ((WPREP_TOTAL + 255) / 256) // 36
#define HIST_BLOCKS ((NEDGES + 255) / 256)       // 3125
#define GBM 64
#define GEMM_BLOCKS ((NNODES + GBM - 1) / GBM)   // 1563

// ============================ helpers ============================

__device__ __forceinline__ uint32_t cvt_bf16x2(float lo, float hi) {
    uint32_t r;
    asm("cvt.rn.satfinite.bf16x2.f32 %0, %1, %2;" : "=r"(r) : "f"(hi), "f"(lo));
    return r;
}

__device__ __forceinline__ void mma_bf16(float* c, const uint32_t* a,
                                         uint32_t b0, uint32_t b1) {
    asm volatile(
        "mma.sync.aligned.m16n8k16.row.col.f32.bf16.bf16.f32 "
        "{%0,%1,%2,%3}, {%4,%5,%6,%7}, {%8,%9}, {%0,%1,%2,%3};"
        : "+f"(c[0]), "+f"(c[1]), "+f"(c[2]), "+f"(c[3])
        : "r"(a[0]), "r"(a[1]), "r"(a[2]), "r"(a[3]), "r"(b0), "r"(b1));
}

// split 4 floats into bf16 hi/lo packed pairs and store to smem
__device__ __forceinline__ void split_store(char* phi, char* plo, int byte_off,
                                            float x, float y, float z, float w) {
    uint32_t h01 = cvt_bf16x2(x, y);
    uint32_t h23 = cvt_bf16x2(z, w);
    float lx = x - __uint_as_float(h01 << 16);
    float ly = y - __uint_as_float(h01 & 0xFFFF0000u);
    float lz = z - __uint_as_float(h23 << 16);
    float lw = w - __uint_as_float(h23 & 0xFFFF0000u);
    *(uint2*)(phi + byte_off) = make_uint2(h01, h23);
    *(uint2*)(plo + byte_off) = make_uint2(cvt_bf16x2(lx, ly), cvt_bf16x2(lz, lw));
}

// ============================ W fragment prep ============================

__device__ __forceinline__ void wprep_body(int idx, const float* __restrict__ W1,
                                           const float* __restrict__ W2) {
    if (idx >= WPREP_TOTAL) return;
    int lane = idx & 31;
    int t = idx >> 5;
    int nt = t % 6;  t /= 6;
    int kt = t % 6;  t /= 6;
    int np = t % 2;  t /= 2;
    int var = t % 2; t /= 2;
    int layer = t;
    const float* W = layer ? W2 : W1;

    int n  = np * 48 + nt * 8 + (lane >> 2);
    int k0 = kt * 16 + (lane & 3) * 2;
    float v[4];
#pragma unroll
    for (int i = 0; i < 4; i++) {
        int k = k0 + (i & 1) + (i >> 1) * 8;
        float w = W[k * DH + n];
        float hi = __bfloat162float(__float2bfloat16(w));
        v[i] = var ? (w - hi) : hi;
    }
    g_Bfrag[idx] = make_uint2(cvt_bf16x2(v[0], v[1]), cvt_bf16x2(v[2], v[3]));
}

// hist (records per-edge slot) || wprep, block-range split
__global__ void hist_wprep_kernel(const int* __restrict__ ei,
                                  const float* __restrict__ W1,
                                  const float* __restrict__ W2) {
    if (blockIdx.x < WPREP_BLOCKS) {
        wprep_body(blockIdx.x * blockDim.x + threadIdx.x, W1, W2);
    } else {
        int e = (blockIdx.x - WPREP_BLOCKS) * blockDim.x + threadIdx.x;
        if (e < NEDGES) {
            int d = ei[NEDGES + e];
            g_epos[e] = atomicAdd(&g_cnt[d], 1);   // count AND slot in one atomic
        }
    }
}

// ============================ scans + fill ============================

#define SCHUNK 512
#define NSBLK ((NNODES + SCHUNK - 1) / SCHUNK)   // 196

__global__ void scan1_kernel() {
    __shared__ int wsum[16];
    const int t = threadIdx.x;
    const int lane = t & 31, warp = t >> 5;
    const int i = blockIdx.x * SCHUNK + t;
    const int v = (i < NNODES) ? g_cnt[i] : 0;
    int x = v;
#pragma unroll
    for (int o = 1; o < 32; o <<= 1) {
        int y = __shfl_up_sync(0xFFFFFFFF, x, o);
        if (lane >= o) x += y;
    }
    if (lane == 31) wsum[warp] = x;
    __syncthreads();
    if (warp == 0) {
        int s = (lane < 16) ? wsum[lane] : 0;
#pragma unroll
        for (int o = 1; o < 16; o <<= 1) {
            int y = __shfl_up_sync(0xFFFFFFFF, s, o);
            if (lane >= o) s += y;
        }
        if (lane < 16) wsum[lane] = s;
    }
    __syncthreads();
    const int base = (warp > 0) ? wsum[warp - 1] : 0;
    if (i < NNODES) {
        g_off[i] = base + x - v;
        g_dis[i] = rsqrtf((float)v + 1.0f);
    }
    if (t == SCHUNK - 1) g_bsum[blockIdx.x] = base + x;
}

__global__ void scan2_kernel() {   // single warp, 7 chunk totals per lane
    const int lane = threadIdx.x;
    const int base = lane * 7;
    int v[7], inc[7];
    int tot = 0;
#pragma unroll
    for (int j = 0; j < 7; j++) {
        v[j] = (base + j < NSBLK) ? g_bsum[base + j] : 0;
        tot += v[j];
        inc[j] = tot;
    }
    int x = tot;
#pragma unroll
    for (int o = 1; o < 32; o <<= 1) {
        int y = __shfl_up_sync(0xFFFFFFFF, x, o);
        if (lane >= o) x += y;
    }
    const int excl = x - tot;
#pragma unroll
    for (int j = 0; j < 7; j++)
        if (base + j < NSBLK) g_bsum[base + j] = excl + inc[j] - v[j];
}

// atomic-free fill: slot was captured during hist
__global__ void fill_kernel(const int* __restrict__ ei) {
    int e = blockIdx.x * blockDim.x + threadIdx.x;
    if (e >= NEDGES) return;
    int s = ei[e];
    int d = ei[NEDGES + e];
    int pos = g_off[d] + g_bsum[d >> 9] + g_epos[e];
    g_csr[pos] = s;
}

// ============================ GEMM (HMMA) ============================
// Hs[n,96] = dis[n] * (A[n,96] @ W[96,96]) stored fp16.
// GBM=64: 8 warps = 2 M-part x 4 N-part, 26.6KB smem.

#define APITCH 104
#define AROW_BYTES (APITCH * 2)
#define SM_AHI 0
#define SM_ALO (GBM * AROW_BYTES)
#define GEMM_SMEM (2 * GBM * AROW_BYTES)   // 26624

__device__ __forceinline__ void gemm_compute(char* smem, int row0,
                                             const uint2* __restrict__ Bfrag,
                                             __half* __restrict__ H) {
    const int tid = threadIdx.x;
    const int lane = tid & 31;
    const int wid = tid >> 5;
    const int wm = wid & 1;            // M partition (32 rows)
    const int wn = wid >> 1;           // N partition (3 nt tiles of 8 cols)

    float acc[2][3][4];
#pragma unroll
    for (int m = 0; m < 2; m++)
#pragma unroll
        for (int nt = 0; nt < 3; nt++)
#pragma unroll
            for (int i = 0; i < 4; i++) acc[m][nt][i] = 0.0f;

    const int fr = (lane >> 2);
    const int fk = (lane & 3) * 2;

#pragma unroll
    for (int kt = 0; kt < 6; kt++) {
        uint32_t ahi[2][4], alo[2][4];
#pragma unroll
        for (int m = 0; m < 2; m++) {
            const int r = wm * 32 + m * 16 + fr;
            const int kb = (kt * 16 + fk) * 2;
            const char* ph = smem + SM_AHI + r * AROW_BYTES + kb;
            const char* pl = smem + SM_ALO + r * AROW_BYTES + kb;
            ahi[m][0] = *(const uint32_t*)ph;
            ahi[m][1] = *(const uint32_t*)(ph + 8 * AROW_BYTES);
            ahi[m][2] = *(const uint32_t*)(ph + 16);
            ahi[m][3] = *(const uint32_t*)(ph + 8 * AROW_BYTES + 16);
            alo[m][0] = *(const uint32_t*)pl;
            alo[m][1] = *(const uint32_t*)(pl + 8 * AROW_BYTES);
            alo[m][2] = *(const uint32_t*)(pl + 16);
            alo[m][3] = *(const uint32_t*)(pl + 8 * AROW_BYTES + 16);
        }
#pragma unroll
        for (int nt = 0; nt < 3; nt++) {
            const int g = wn * 3 + nt;          // global 8-col tile 0..11
            const int np = g / 6, n6 = g % 6;
            const uint2 bhi = Bfrag[(((0 * 2 + np) * 6 + kt) * 6 + n6) * 32 + lane];
            const uint2 blo = Bfrag[(((1 * 2 + np) * 6 + kt) * 6 + n6) * 32 + lane];
#pragma unroll
            for (int m = 0; m < 2; m++) {
                mma_bf16(acc[m][nt], ahi[m], bhi.x, bhi.y);
                mma_bf16(acc[m][nt], ahi[m], blo.x, blo.y);
                mma_bf16(acc[m][nt], alo[m], bhi.x, bhi.y);
            }
        }
    }

#pragma unroll
    for (int m = 0; m < 2; m++) {
        const int r = row0 + wm * 32 + m * 16 + fr;
        const float d0 = (r < NNODES) ? g_dis[r] : 0.0f;
        const float d1 = (r + 8 < NNODES) ? g_dis[r + 8] : 0.0f;
#pragma unroll
        for (int nt = 0; nt < 3; nt++) {
            const int col = (wn * 3 + nt) * 8 + fk;
            if (r < NNODES)
                *(__half2*)(H + (size_t)r * DH + col) =
                    __floats2half2_rn(acc[m][nt][0] * d0, acc[m][nt][1] * d0);
            if (r + 8 < NNODES)
                *(__half2*)(H + (size_t)(r + 8) * DH + col) =
                    __floats2half2_rn(acc[m][nt][2] * d1, acc[m][nt][3] * d1);
        }
    }
}

// layer-1 GEMM: stage A from gmem fp32 x, split bf16, compute
__global__ void __launch_bounds__(256)
gemm_f32_kernel(const float* __restrict__ A, const uint2* __restrict__ Bfrag,
                __half* __restrict__ H) {
    extern __shared__ char smem[];
    const int tid = threadIdx.x;
    const int row0 = blockIdx.x * GBM;
    {
        const int r = tid >> 2;            // 0..63
        const int cb = (tid & 3) * 24;     // 24-col segment
        const int grow = row0 + r;
        char* phi = smem + SM_AHI + r * AROW_BYTES;
        char* plo = smem + SM_ALO + r * AROW_BYTES;
#pragma unroll
        for (int q = 0; q < 6; q++) {
            const int k0 = cb + q * 4;
            float4 v = (grow < NNODES)
                ? *(const float4*)(A + (size_t)grow * DH + k0)
                : make_float4(0.f, 0.f, 0.f, 0.f);
            split_store(phi, plo, k0 * 2, v.x, v.y, v.z, v.w);
        }
    }
    __syncthreads();
    gemm_compute(smem, row0, Bfrag, H);
}

// layer-2 GEMM: stage A from fp16 activations (bias/relu already applied)
__global__ void __launch_bounds__(256)
gemm_f16_kernel(const __half* __restrict__ A, const uint2* __restrict__ Bfrag,
                __half* __restrict__ H) {
    extern __shared__ char smem[];
    const int tid = threadIdx.x;
    const int row0 = blockIdx.x * GBM;
    {
        const int r = tid >> 2;            // 0..63
        const int cb = (tid & 3) * 24;     // 24-col segment
        const int grow = row0 + r;
        char* phi = smem + SM_AHI + r * AROW_BYTES;
        char* plo = smem + SM_ALO + r * AROW_BYTES;
#pragma unroll
        for (int q = 0; q < 6; q++) {
            const int k0 = cb + q * 4;
            float4 v = make_float4(0.f, 0.f, 0.f, 0.f);
            if (grow < NNODES) {
                uint2 u = *(const uint2*)(A + (size_t)grow * DH + k0);   // 4 halves
                float2 f0 = __half22float2(*reinterpret_cast<__half2*>(&u.x));
                float2 f1 = __half22float2(*reinterpret_cast<__half2*>(&u.y));
                v = make_float4(f0.x, f0.y, f1.x, f1.y);
            }
            split_store(phi, plo, k0 * 2, v.x, v.y, v.z, v.w);
        }
    }
    __syncthreads();
    gemm_compute(smem, row0, Bfrag, H);
}

// ============================ gather aggregation ============================
// One warp per node, fp16 H table, fp32 accumulation.
// r = relu(dis[d] * (Hs[d] + sum Hs[s]) + bias)
// mode 0: out16[d] = fp16(r) (layer-1 activation for gemm2)
// mode 1: out32[d] = r       (final fp32 output)

__global__ void __launch_bounds__(256)
gather_kernel(const __half* __restrict__ Hin, const float* __restrict__ bias,
              __half* __restrict__ out16, float* __restrict__ out32, int mode) {
    int gwid = (blockIdx.x * blockDim.x + threadIdx.x) >> 5;
    int lid = threadIdx.x & 31;
    if (gwid >= NNODES) return;

    const bool active = lid < C4;
    float4 acc = make_float4(0.f, 0.f, 0.f, 0.f);
    if (active) {
        uint2 u = __ldg((const uint2*)(Hin + (size_t)gwid * DH) + lid);  // self
        float2 f0 = __half22float2(*reinterpret_cast<__half2*>(&u.x));
        float2 f1 = __half22float2(*reinterpret_cast<__half2*>(&u.y));
        acc = make_float4(f0.x, f0.y, f1.x, f1.y);
    }

    int start = g_off[gwid] + g_bsum[gwid >> 9];
    int deg   = g_cnt[gwid];
#pragma unroll 4
    for (int i = 0; i < deg; i++) {
        int s = __ldg(&g_csr[start + i]);
        if (active) {
            uint2 u = __ldg((const uint2*)(Hin + (size_t)s * DH) + lid);
            float2 f0 = __half22float2(*reinterpret_cast<__half2*>(&u.x));
            float2 f1 = __half22float2(*reinterpret_cast<__half2*>(&u.y));
            acc.x += f0.x; acc.y += f0.y; acc.z += f1.x; acc.w += f1.y;
        }
    }

    if (active) {
        float dd = g_dis[gwid];
        float4 b = __ldg((const float4*)bias + lid);
        acc.x = fmaxf(acc.x * dd + b.x, 0.0f);
        acc.y = fmaxf(acc.y * dd + b.y, 0.0f);
        acc.z = fmaxf(acc.z * dd + b.z, 0.0f);
        acc.w = fmaxf(acc.w * dd + b.w, 0.0f);
        if (mode == 0) {
            uint2 u;
            *reinterpret_cast<__half2*>(&u.x) = __floats2half2_rn(acc.x, acc.y);
            *reinterpret_cast<__half2*>(&u.y) = __floats2half2_rn(acc.z, acc.w);
            ((uint2*)(out16 + (size_t)gwid * DH))[lid] = u;
        } else {
            ((float4*)(out32 + (size_t)gwid * DH))[lid] = acc;
        }
    }
}

// ============================ launch ============================

extern "C" void kernel_launch(void* const* d_in, const int* in_sizes, int n_in,
                              void* d_out, int out_size) {
    const float* x  = (const float*)d_in[0];
    const int*   ei = (const int*)d_in[1];
    const float* W1 = (const float*)d_in[2];
    const float* b1 = (const float*)d_in[3];
    const float* W2 = (const float*)d_in[4];
    const float* b2 = (const float*)d_in[5];
    float* out = (float*)d_out;

    void *pH_v, *pAGG_v, *pBf_v, *pCnt_v;
    cudaGetSymbolAddress(&pH_v, g_H);
    cudaGetSymbolAddress(&pAGG_v, g_AGG);
    cudaGetSymbolAddress(&pBf_v, g_Bfrag);
    cudaGetSymbolAddress(&pCnt_v, g_cnt);
    __half* pH   = (__half*)pH_v;
    __half* pAGG = (__half*)pAGG_v;
    const uint2* pBf = (const uint2*)pBf_v;

    cudaFuncSetAttribute(gemm_f32_kernel,
                         cudaFuncAttributeMaxDynamicSharedMemorySize, GEMM_SMEM);
    cudaFuncSetAttribute(gemm_f16_kernel,
                         cudaFuncAttributeMaxDynamicSharedMemorySize, GEMM_SMEM);

    const int T = 256;
    int nBlkGath = (NNODES * 32 + T - 1) / T;

    // 1. zero cnt
    cudaMemsetAsync(pCnt_v, 0, NNODES * sizeof(int));
    // 2. hist (+ per-edge slot capture) || wprep
    hist_wprep_kernel<<<WPREP_BLOCKS + HIST_BLOCKS, T>>>(ei, W1, W2);
    // 3-4. scans (+ dis)
    scan1_kernel<<<NSBLK, SCHUNK>>>();
    scan2_kernel<<<1, 32>>>();
    // 5. CSR fill (atomic-free)
    fill_kernel<<<HIST_BLOCKS, T>>>(ei);
    // 6. layer-1 GEMM: g_H = fp16(dis * (x @ W1))
    gemm_f32_kernel<<<GEMM_BLOCKS, T, GEMM_SMEM>>>(x, pBf, pH);
    // 7. gather layer 1 -> g_AGG = fp16(relu(agg + b1))
    gather_kernel<<<nBlkGath, T>>>(pH, b1, pAGG, nullptr, 0);
    // 8. layer-2 GEMM (fp16 A): g_H = fp16(dis * (AGG @ W2))
    gemm_f16_kernel<<<GEMM_BLOCKS, T, GEMM_SMEM>>>(pAGG, pBf + 4608, pH);
    // 9. gather layer 2 (bias+relu) -> out (fp32)
    gather_kernel<<<nBlkGath, T>>>(pH, b2, nullptr, out, 1);
}